// round 9
// baseline (speedup 1.0000x reference)
#include <cuda_runtime.h>
#include <cuda_fp16.h>
#include <cstdint>

// ============================================================
// QuaternionLinear as one 4096x4096x4096 fp16 GEMM (mma.sync)
//   out = x_flat(4096x4096) @ W'^T(4096x4096) + bias
// R8: R3 config (128x256 CTA, 8 warps 64x64, 3x64K stages) +
//     fp16-ACCUMULATE mma (2x HMMA rate) with 256-K chunked
//     promotion into fp32 master accumulators.
// ============================================================

#define BATCH   4096
#define KDIM    4096
#define NDIM    4096

#define BM      128
#define BN      256
#define BK      64          // halves per K-tile (128 bytes per row)
#define NK      (KDIM / BK) // 64
#define STAGES  3
#define NTHREADS 256
#define PROMO   4           // promote fp16 chunk acc every 4 k-iters (256 K)

#define A_TILE_BYTES (BM * 128)   // 16384
#define B_TILE_BYTES (BN * 128)   // 32768
#define STAGE_BYTES  (A_TILE_BYTES + B_TILE_BYTES)   // 49152
#define SMEM_TOTAL   (STAGES * STAGE_BYTES)          // 147456

// fp16 scratch (device globals: allocation-free per harness rules)
__device__ __align__(128) __half g_Ah[(size_t)BATCH * KDIM];
__device__ __align__(128) __half g_Bh[(size_t)NDIM * KDIM];

// ---------------- helpers ----------------
__device__ __forceinline__ uint32_t smem_u32(const void* p) {
    uint32_t a;
    asm("{ .reg .u64 t; cvta.to.shared.u64 t, %1; cvt.u32.u64 %0, t; }" : "=r"(a) : "l"(p));
    return a;
}
__device__ __forceinline__ void cp_async16(uint32_t dst, const void* src) {
    asm volatile("cp.async.cg.shared.global [%0], [%1], 16;\n" :: "r"(dst), "l"(src));
}
#define CP_COMMIT() asm volatile("cp.async.commit_group;\n" ::: "memory")
#define CP_WAIT(n)  asm volatile("cp.async.wait_group %0;\n" :: "n"(n) : "memory")

__device__ __forceinline__ void ldm_x4(uint32_t* r, uint32_t addr) {
    asm volatile("ldmatrix.sync.aligned.m8n8.x4.shared.b16 {%0,%1,%2,%3}, [%4];"
        : "=r"(r[0]), "=r"(r[1]), "=r"(r[2]), "=r"(r[3]) : "r"(addr));
}
// fp16-accumulate HMMA: D(fp16x4 in 2 regs) = A*B + C
__device__ __forceinline__ void mma16816_f16(uint32_t* c, const uint32_t* a, const uint32_t* b) {
    asm volatile(
        "mma.sync.aligned.m16n8k16.row.col.f16.f16.f16.f16 "
        "{%0,%1}, {%2,%3,%4,%5}, {%6,%7}, {%0,%1};"
        : "+r"(c[0]), "+r"(c[1])
        : "r"(a[0]), "r"(a[1]), "r"(a[2]), "r"(a[3]), "r"(b[0]), "r"(b[1]));
}
__device__ __forceinline__ uint32_t sw128(uint32_t off) {
    return off ^ ((off >> 3) & 0x70);
}

// ---------------- Prep kernels ----------------
__global__ void convert_x_kernel(const float4* __restrict__ x) {
    int i = blockIdx.x * blockDim.x + threadIdx.x;
    if (i >= (BATCH * KDIM) / 4) return;
    float4 v = x[i];
    __half2* dst = reinterpret_cast<__half2*>(g_Ah);
    dst[2 * i]     = __floats2half2_rn(v.x, v.y);
    dst[2 * i + 1] = __floats2half2_rn(v.z, v.w);
}

__global__ void build_w_kernel(const float4* __restrict__ w) {
    int gid = blockIdx.x * blockDim.x + threadIdx.x;  // (oc, i)
    if (gid >= NDIM * 1024) return;
    int i  = gid & 1023;
    int oc = gid >> 10;
    int c  = oc & 3;
    int o  = oc >> 2;
    float4 v = w[o * 1024 + i];
    float wv[4] = {v.x, v.y, v.z, v.w};
    // out_c coefficient of a_d is sign[c][d] * w[comp[c][d]]
    const int  comp[4][4] = {{0,1,2,3},{1,0,3,2},{2,3,0,1},{3,2,1,0}};
    const float sgn[4][4] = {{1.f,-1.f,-1.f,-1.f},{1.f,1.f,1.f,-1.f},
                             {1.f,-1.f,1.f,1.f},{1.f,1.f,-1.f,1.f}};
    __half2* dst = reinterpret_cast<__half2*>(g_Bh);
    dst[2 * gid]     = __floats2half2_rn(sgn[c][0]*wv[comp[c][0]], sgn[c][1]*wv[comp[c][1]]);
    dst[2 * gid + 1] = __floats2half2_rn(sgn[c][2]*wv[comp[c][2]], sgn[c][3]*wv[comp[c][3]]);
}

// ---------------- GEMM ----------------
__device__ __forceinline__ void load_stage(uint32_t sbase, int slot, int kt,
                                           int m0, int n0, int tid) {
    uint32_t st = sbase + slot * STAGE_BYTES;
    int k0 = kt * BK;
    const __half* Ap = g_Ah + ((size_t)m0 << 12) + k0;
    const __half* Bp = g_Bh + ((size_t)n0 << 12) + k0;
#pragma unroll
    for (int c = 0; c < BM * 8; c += NTHREADS) {     // A: 1024 16B chunks
        int cc = c + tid;
        int row = cc >> 3, col = cc & 7;
        uint32_t sw = sw128((uint32_t)((row << 7) | (col << 4)));
        cp_async16(st + sw, Ap + ((size_t)row << 12) + (col << 3));
    }
#pragma unroll
    for (int c = 0; c < BN * 8; c += NTHREADS) {     // B: 2048 16B chunks
        int cc = c + tid;
        int row = cc >> 3, col = cc & 7;
        uint32_t sw = sw128((uint32_t)((row << 7) | (col << 4)));
        cp_async16(st + A_TILE_BYTES + sw, Bp + ((size_t)row << 12) + (col << 3));
    }
}

__global__ void __launch_bounds__(NTHREADS, 1) qgemm_kernel(const float* __restrict__ bias,
                                                            float* __restrict__ out) {
    extern __shared__ char smem[];
    uint32_t sbase = smem_u32(smem);
    int tid = threadIdx.x;
    int wid = tid >> 5;
    int lid = tid & 31;
    int m0 = blockIdx.y * BM;
    int n0 = blockIdx.x * BN;

    int warp_m = wid & 1;   // 2 warps along M (64 rows each)
    int warp_n = wid >> 1;  // 4 warps along N (64 cols each)

    float acc[4][8][4];     // fp32 master accumulators
    uint32_t cf[4][8][2];   // fp16 chunk accumulators (4 halves per tile)
#pragma unroll
    for (int i = 0; i < 4; ++i)
#pragma unroll
        for (int j = 0; j < 8; ++j) {
#pragma unroll
            for (int v = 0; v < 4; ++v) acc[i][j][v] = 0.f;
            cf[i][j][0] = 0u; cf[i][j][1] = 0u;
        }

    // Prologue: stages 0 .. STAGES-2
#pragma unroll
    for (int s = 0; s < STAGES - 1; ++s) {
        load_stage(sbase, s, s, m0, n0, tid);
        CP_COMMIT();
    }

    // Per-lane ldmatrix address components
    int a_mat = lid >> 3;            // 0..3
    int a_r   = lid & 7;
    int a_row_base = warp_m * 64 + (a_mat & 1) * 8 + a_r;   // + mt*16
    int a_kb_base  = (a_mat >> 1) * 16;                     // byte offset of k within row
    int b_row_base = warp_n * 64 + (a_mat >> 1) * 8 + a_r;  // + ntp*16
    int b_kb_base  = (a_mat & 1) * 16;

    for (int k = 0; k < NK; ++k) {
        CP_WAIT(STAGES - 2);
        __syncthreads();
        // Loads for stage k+STAGES-1 overwrite the stage consumed at iter k-1;
        // the sync above proves all warps are done with it.
        int kload = k + STAGES - 1;
        if (kload < NK) load_stage(sbase, kload % STAGES, kload, m0, n0, tid);
        CP_COMMIT();

        uint32_t a_base = sbase + (k % STAGES) * STAGE_BYTES;
        uint32_t b_base = a_base + A_TILE_BYTES;

#pragma unroll
        for (int ks = 0; ks < BK / 16; ++ks) {
            int kb = ks * 32;   // byte offset of k-chunk within 128B row
            uint32_t af[4][4];
#pragma unroll
            for (int mt = 0; mt < 4; ++mt) {
                uint32_t off = (uint32_t)((a_row_base + mt * 16) << 7) + kb + a_kb_base;
                ldm_x4(af[mt], a_base + sw128(off));
            }
            uint32_t bf[4][4];
#pragma unroll
            for (int ntp = 0; ntp < 4; ++ntp) {
                uint32_t off = (uint32_t)((b_row_base + ntp * 16) << 7) + kb + b_kb_base;
                ldm_x4(bf[ntp], b_base + sw128(off));
            }
#pragma unroll
            for (int mt = 0; mt < 4; ++mt)
#pragma unroll
                for (int nt = 0; nt < 8; ++nt)
                    mma16816_f16(cf[mt][nt], af[mt], &bf[nt >> 1][(nt & 1) * 2]);
        }

        // Promote fp16 chunk accumulators to fp32 every PROMO k-iters (256 K)
        if ((k & (PROMO - 1)) == PROMO - 1) {
#pragma unroll
            for (int mt = 0; mt < 4; ++mt)
#pragma unroll
                for (int nt = 0; nt < 8; ++nt) {
                    __half2 h0 = *reinterpret_cast<__half2*>(&cf[mt][nt][0]);
                    __half2 h1 = *reinterpret_cast<__half2*>(&cf[mt][nt][1]);
                    float2 f0 = __half22float2(h0);
                    float2 f1 = __half22float2(h1);
                    acc[mt][nt][0] += f0.x;
                    acc[mt][nt][1] += f0.y;
                    acc[mt][nt][2] += f1.x;
                    acc[mt][nt][3] += f1.y;
                    cf[mt][nt][0] = 0u; cf[mt][nt][1] = 0u;
                }
        }
    }

    // Epilogue: float2 stores + bias (NK divisible by PROMO -> cf already drained)
    int qrow = lid >> 2;        // 0..7
    int qcol = (lid & 3) * 2;   // 0,2,4,6
#pragma unroll
    for (int nt = 0; nt < 8; ++nt) {
        int gn = n0 + warp_n * 64 + nt * 8 + qcol;
        float b0 = __ldg(bias + gn);
        float b1 = __ldg(bias + gn + 1);
#pragma unroll
        for (int mt = 0; mt < 4; ++mt) {
            int gm = m0 + warp_m * 64 + mt * 16 + qrow;
            float2 v0 = {acc[mt][nt][0] + b0, acc[mt][nt][1] + b1};
            float2 v1 = {acc[mt][nt][2] + b0, acc[mt][nt][3] + b1};
            *reinterpret_cast<float2*>(out + (size_t)gm * NDIM + gn) = v0;
            *reinterpret_cast<float2*>(out + (size_t)(gm + 8) * NDIM + gn) = v1;
        }
    }
}

// ---------------- launch ----------------
extern "C" void kernel_launch(void* const* d_in, const int* in_sizes, int n_in,
                              void* d_out, int out_size) {
    const float* x    = (const float*)d_in[0];
    const float* w    = (const float*)d_in[1];
    const float* bias = (const float*)d_in[2];
    float* out = (float*)d_out;

    convert_x_kernel<<<(BATCH * KDIM / 4 + 255) / 256, 256>>>((const float4*)x);
    build_w_kernel<<<(NDIM * 1024 + 255) / 256, 256>>>((const float4*)w);

    cudaFuncSetAttribute(qgemm_kernel, cudaFuncAttributeMaxDynamicSharedMemorySize, SMEM_TOTAL);
    dim3 grid(NDIM / BN, BATCH / BM);   // (16, 32)
    qgemm_kernel<<<grid, NTHREADS, SMEM_TOTAL>>>(bias, out);
}

// round 10
// speedup vs baseline: 1.3153x; 1.3153x over previous
#include <cuda_runtime.h>
#include <cuda_fp16.h>
#include <cstdint>

// ============================================================
// QuaternionLinear via 12-mult Cayley-Dickson/Gauss decomposition.
// out components come from 12 bilinear GEMMs (75% of the naive 16),
// organized as 2 GEMMs of M=4096, N=1024, K=6144 with a mid-loop
// accumulator snapshot:
//   variant0 (out_r,out_i): A=[q0..q5], B0=[br|-bj|-(br+bi)|bj-bk|bi-br|bj+bk]
//   variant1 (out_j,out_k): A=[q0..q5], B1=[bj|br|-(bj+bk)|bi-br|bk-bj|-(br+bi)]
//   q = [ar+ai, aj+ak, ai, ak, ar, aj]
//   R accumulates K-blocks 0..3;  I <- R after block 1;  I accumulates 4..5.
// Classic mma.sync fp32-accumulate path (tcgen05 blocked by compute_103).
// ============================================================

#define BATCH   4096
#define KTOT    6144          // 6 blocks x 1024
#define NOUT    1024          // o dimension per variant

#define BM      128
#define BN      128
#define BK      64            // halves per K-tile (128B rows)
#define NK      (KTOT / BK)   // 96
#define STAGES  3
#define NTHREADS 256

#define A_TILE_BYTES (BM * 128)   // 16384
#define B_TILE_BYTES (BN * 128)   // 16384
#define STAGE_BYTES  (A_TILE_BYTES + B_TILE_BYTES)   // 32768
#define SMEM_TOTAL   (STAGES * STAGE_BYTES)          // 98304

// device-global scratch (allocation-free per harness rules)
__device__ __align__(128) __half g_A [(size_t)BATCH * KTOT];   // 50.3 MB
__device__ __align__(128) __half g_B0[(size_t)NOUT  * KTOT];   // 12.6 MB
__device__ __align__(128) __half g_B1[(size_t)NOUT  * KTOT];   // 12.6 MB

// ---------------- helpers ----------------
__device__ __forceinline__ uint32_t smem_u32(const void* p) {
    uint32_t a;
    asm("{ .reg .u64 t; cvta.to.shared.u64 t, %1; cvt.u32.u64 %0, t; }" : "=r"(a) : "l"(p));
    return a;
}
__device__ __forceinline__ void cp_async16(uint32_t dst, const void* src) {
    asm volatile("cp.async.cg.shared.global [%0], [%1], 16;\n" :: "r"(dst), "l"(src));
}
#define CP_COMMIT() asm volatile("cp.async.commit_group;\n" ::: "memory")
#define CP_WAIT(n)  asm volatile("cp.async.wait_group %0;\n" :: "n"(n) : "memory")

__device__ __forceinline__ void ldm_x4(uint32_t* r, uint32_t addr) {
    asm volatile("ldmatrix.sync.aligned.m8n8.x4.shared.b16 {%0,%1,%2,%3}, [%4];"
        : "=r"(r[0]), "=r"(r[1]), "=r"(r[2]), "=r"(r[3]) : "r"(addr));
}
__device__ __forceinline__ void mma16816(float* c, const uint32_t* a, const uint32_t* b) {
    asm volatile(
        "mma.sync.aligned.m16n8k16.row.col.f32.f16.f16.f32 "
        "{%0,%1,%2,%3}, {%4,%5,%6,%7}, {%8,%9}, {%0,%1,%2,%3};"
        : "+f"(c[0]), "+f"(c[1]), "+f"(c[2]), "+f"(c[3])
        : "r"(a[0]), "r"(a[1]), "r"(a[2]), "r"(a[3]), "r"(b[0]), "r"(b[1]));
}
__device__ __forceinline__ uint32_t sw128(uint32_t off) {
    return off ^ ((off >> 3) & 0x70);
}
__device__ __forceinline__ __half2 h2(float a, float b) { return __floats2half2_rn(a, b); }

// ---------------- Prep: A planes ----------------
// threads over (b, i-pair): 4096 x 512
__global__ void prep_a_kernel(const float4* __restrict__ x) {
    int t = blockIdx.x * blockDim.x + threadIdx.x;
    if (t >= BATCH * 512) return;
    int b  = t >> 9;
    int ip = (t & 511) << 1;
    const float4* xr = x + ((size_t)b * 1024 + ip);
    float4 v0 = xr[0], v1 = xr[1];   // (ar,ai,aj,ak) for i=ip, ip+1
    __half* row = g_A + (size_t)b * KTOT;
    *reinterpret_cast<__half2*>(row +    0 + ip) = h2(v0.x + v0.y, v1.x + v1.y); // ar+ai
    *reinterpret_cast<__half2*>(row + 1024 + ip) = h2(v0.z + v0.w, v1.z + v1.w); // aj+ak
    *reinterpret_cast<__half2*>(row + 2048 + ip) = h2(v0.y, v1.y);               // ai
    *reinterpret_cast<__half2*>(row + 3072 + ip) = h2(v0.w, v1.w);               // ak
    *reinterpret_cast<__half2*>(row + 4096 + ip) = h2(v0.x, v1.x);               // ar
    *reinterpret_cast<__half2*>(row + 5120 + ip) = h2(v0.z, v1.z);               // aj
}

// ---------------- Prep: B planes (signs folded) ----------------
// threads over (o, i-pair): 1024 x 512
__global__ void prep_b_kernel(const float4* __restrict__ w) {
    int t = blockIdx.x * blockDim.x + threadIdx.x;
    if (t >= NOUT * 512) return;
    int o  = t >> 9;
    int ip = (t & 511) << 1;
    const float4* wr = w + ((size_t)o * 1024 + ip);
    float4 v0 = wr[0], v1 = wr[1];   // (br,bi,bj,bk)
    __half* r0 = g_B0 + (size_t)o * KTOT;
    __half* r1 = g_B1 + (size_t)o * KTOT;
    // variant 0: [ br | -bj | -(br+bi) | bj-bk | bi-br | bj+bk ]
    *reinterpret_cast<__half2*>(r0 +    0 + ip) = h2( v0.x,           v1.x);
    *reinterpret_cast<__half2*>(r0 + 1024 + ip) = h2(-v0.z,          -v1.z);
    *reinterpret_cast<__half2*>(r0 + 2048 + ip) = h2(-(v0.x + v0.y), -(v1.x + v1.y));
    *reinterpret_cast<__half2*>(r0 + 3072 + ip) = h2( v0.z - v0.w,    v1.z - v1.w);
    *reinterpret_cast<__half2*>(r0 + 4096 + ip) = h2( v0.y - v0.x,    v1.y - v1.x);
    *reinterpret_cast<__half2*>(r0 + 5120 + ip) = h2( v0.z + v0.w,    v1.z + v1.w);
    // variant 1: [ bj | br | -(bj+bk) | bi-br | bk-bj | -(br+bi) ]
    *reinterpret_cast<__half2*>(r1 +    0 + ip) = h2( v0.z,           v1.z);
    *reinterpret_cast<__half2*>(r1 + 1024 + ip) = h2( v0.x,           v1.x);
    *reinterpret_cast<__half2*>(r1 + 2048 + ip) = h2(-(v0.z + v0.w), -(v1.z + v1.w));
    *reinterpret_cast<__half2*>(r1 + 3072 + ip) = h2( v0.y - v0.x,    v1.y - v1.x);
    *reinterpret_cast<__half2*>(r1 + 4096 + ip) = h2( v0.w - v0.z,    v1.w - v1.z);
    *reinterpret_cast<__half2*>(r1 + 5120 + ip) = h2(-(v0.x + v0.y), -(v1.x + v1.y));
}

// ---------------- GEMM ----------------
__device__ __forceinline__ void load_stage(uint32_t sbase, int slot, int kt,
                                           int m0, int n0, int tid,
                                           const __half* __restrict__ Bmat) {
    uint32_t st = sbase + slot * STAGE_BYTES;
    int k0 = kt * BK;
    const __half* Ap = g_A  + (size_t)m0 * KTOT + k0;
    const __half* Bp = Bmat + (size_t)n0 * KTOT + k0;
#pragma unroll
    for (int c = 0; c < BM * 8; c += NTHREADS) {     // A: 1024 16B chunks
        int cc = c + tid;
        int row = cc >> 3, col = cc & 7;
        uint32_t sw = sw128((uint32_t)((row << 7) | (col << 4)));
        cp_async16(st + sw, Ap + (size_t)row * KTOT + (col << 3));
    }
#pragma unroll
    for (int c = 0; c < BN * 8; c += NTHREADS) {     // B: 1024 16B chunks
        int cc = c + tid;
        int row = cc >> 3, col = cc & 7;
        uint32_t sw = sw128((uint32_t)((row << 7) | (col << 4)));
        cp_async16(st + A_TILE_BYTES + sw, Bp + (size_t)row * KTOT + (col << 3));
    }
}

// One k-iteration: pipeline maintenance + 4 k-steps of mma into ACC.
#define KBODY(ACC, kvar)                                                          \
    do {                                                                          \
        CP_WAIT(STAGES - 2);                                                      \
        __syncthreads();                                                          \
        int kload = (kvar) + STAGES - 1;                                          \
        if (kload < NK) load_stage(sbase, kload % STAGES, kload, m0, n0, tid, Bmat); \
        CP_COMMIT();                                                              \
        uint32_t a_base = sbase + ((kvar) % STAGES) * STAGE_BYTES;                \
        uint32_t b_base = a_base + A_TILE_BYTES;                                  \
        _Pragma("unroll")                                                         \
        for (int ks = 0; ks < BK / 16; ++ks) {                                    \
            int kb = ks * 32;                                                     \
            uint32_t af[4][4];                                                    \
            _Pragma("unroll")                                                     \
            for (int mt = 0; mt < 4; ++mt) {                                      \
                uint32_t off = (uint32_t)((a_row_base + mt * 16) << 7) + kb + a_kb_base; \
                ldm_x4(af[mt], a_base + sw128(off));                              \
            }                                                                     \
            uint32_t bf[8];                                                       \
            _Pragma("unroll")                                                     \
            for (int ntp = 0; ntp < 2; ++ntp) {                                   \
                uint32_t off = (uint32_t)((b_row_base + ntp * 16) << 7) + kb + b_kb_base; \
                ldm_x4(&bf[ntp * 4], b_base + sw128(off));                        \
            }                                                                     \
            _Pragma("unroll")                                                     \
            for (int mt = 0; mt < 4; ++mt)                                        \
                _Pragma("unroll")                                                 \
                for (int nt = 0; nt < 4; ++nt)                                    \
                    mma16816(ACC[mt][nt], af[mt], &bf[nt * 2]);                   \
        }                                                                         \
    } while (0)

__global__ void __launch_bounds__(NTHREADS, 1) qgemm_kernel(const float* __restrict__ bias,
                                                            float* __restrict__ out) {
    extern __shared__ char smem[];
    uint32_t sbase = smem_u32(smem);
    int tid = threadIdx.x;
    int wid = tid >> 5;
    int lid = tid & 31;
    int m0 = blockIdx.y * BM;      // batch rows
    int n0 = blockIdx.x * BN;      // o columns
    const __half* Bmat = blockIdx.z ? g_B1 : g_B0;

    int warp_m = wid & 1;   // 2 warps along M (64 rows each)
    int warp_n = wid >> 1;  // 4 warps along N (32 cols each)

    float accR[4][4][4];    // out_r (variant0) / out_j (variant1)
    float accI[4][4][4];    // out_i / out_k
#pragma unroll
    for (int i = 0; i < 4; ++i)
#pragma unroll
        for (int j = 0; j < 4; ++j)
#pragma unroll
            for (int v = 0; v < 4; ++v) accR[i][j][v] = 0.f;

    // Prologue: stages 0 .. STAGES-2
#pragma unroll
    for (int s = 0; s < STAGES - 1; ++s) {
        load_stage(sbase, s, s, m0, n0, tid, Bmat);
        CP_COMMIT();
    }

    // Per-lane ldmatrix address components (R2 geometry: warp 64x32)
    int a_mat = lid >> 3;            // 0..3
    int a_r   = lid & 7;
    int a_row_base = warp_m * 64 + (a_mat & 1) * 8 + a_r;   // + mt*16
    int a_kb_base  = (a_mat >> 1) * 16;
    int b_row_base = warp_n * 32 + (a_mat >> 1) * 8 + a_r;  // + ntp*16
    int b_kb_base  = (a_mat & 1) * 16;

    // Phase 1: K-blocks 0..1 (shared Gauss term) -> accR
    for (int k = 0; k < 32; ++k) KBODY(accR, k);

    // Snapshot: accI <- accR
#pragma unroll
    for (int i = 0; i < 4; ++i)
#pragma unroll
        for (int j = 0; j < 4; ++j)
#pragma unroll
            for (int v = 0; v < 4; ++v) accI[i][j][v] = accR[i][j][v];

    // Phase 2: K-blocks 2..3 -> accR (completes out_r / out_j)
    for (int k = 32; k < 64; ++k) KBODY(accR, k);

    // Phase 3: K-blocks 4..5 -> accI (completes out_i / out_k)
    for (int k = 64; k < NK; ++k) KBODY(accI, k);

    // Epilogue: component pair (2z, 2z+1) interleaved stores + bias
    int zc = (int)blockIdx.z * 2;
    int qrow = lid >> 2;        // 0..7
    int qcol = (lid & 3) * 2;   // 0,2,4,6
#pragma unroll
    for (int nt = 0; nt < 4; ++nt) {
        int o = n0 + warp_n * 32 + nt * 8 + qcol;   // o, o+1
        float b00 = __ldg(bias + o * 4 + zc);
        float b01 = __ldg(bias + o * 4 + zc + 1);
        float b10 = __ldg(bias + (o + 1) * 4 + zc);
        float b11 = __ldg(bias + (o + 1) * 4 + zc + 1);
#pragma unroll
        for (int mt = 0; mt < 4; ++mt) {
            int gm = m0 + warp_m * 64 + mt * 16 + qrow;
            float* p0 = out + (size_t)gm * 4096 + o * 4 + zc;
            float* p1 = out + (size_t)(gm + 8) * 4096 + o * 4 + zc;
            float2 v;
            v.x = accR[mt][nt][0] + b00; v.y = accI[mt][nt][0] + b01;
            *reinterpret_cast<float2*>(p0) = v;
            v.x = accR[mt][nt][1] + b10; v.y = accI[mt][nt][1] + b11;
            *reinterpret_cast<float2*>(p0 + 4) = v;
            v.x = accR[mt][nt][2] + b00; v.y = accI[mt][nt][2] + b01;
            *reinterpret_cast<float2*>(p1) = v;
            v.x = accR[mt][nt][3] + b10; v.y = accI[mt][nt][3] + b11;
            *reinterpret_cast<float2*>(p1 + 4) = v;
        }
    }
}

// ---------------- launch ----------------
extern "C" void kernel_launch(void* const* d_in, const int* in_sizes, int n_in,
                              void* d_out, int out_size) {
    const float* x    = (const float*)d_in[0];
    const float* w    = (const float*)d_in[1];
    const float* bias = (const float*)d_in[2];
    float* out = (float*)d_out;

    prep_a_kernel<<<(BATCH * 512 + 255) / 256, 256>>>((const float4*)x);
    prep_b_kernel<<<(NOUT * 512 + 255) / 256, 256>>>((const float4*)w);

    cudaFuncSetAttribute(qgemm_kernel, cudaFuncAttributeMaxDynamicSharedMemorySize, SMEM_TOTAL);
    dim3 grid(NOUT / BN, BATCH / BM, 2);   // (8, 32, 2) = 512 CTAs
    qgemm_kernel<<<grid, NTHREADS, SMEM_TOTAL>>>(bias, out);
}